// round 5
// baseline (speedup 1.0000x reference)
#include <cuda_runtime.h>
#include <math.h>

#define VP 196
#define TLN 316
#define SQ 512
#define VD 1024
#define HDIM 768
#define NHEAD 8
#define HD 96
#define FFD 3072
#define NLAYER 6
#define NB 16
#define MROWS (NB*SQ)   /* 8192 */

// ---------------- scratch (device globals; no allocations) ----------------
__device__ float g_x[MROWS*HDIM];        // 25.2 MB  residual stream
__device__ float g_y[MROWS*HDIM];        // 25.2 MB  attn-out / ffn-out
__device__ float g_qkv[MROWS*3*HDIM];    // 75.5 MB
__device__ float g_h[MROWS*FFD];         // 100.7 MB ffn hidden / proj tmp
__device__ float g_sc[NB*NHEAD*SQ*SQ];   // 134 MB   attention scores
__device__ float g_bias[NB*SQ];          // key-padding bias

// ---------------- helpers ----------------
__device__ __forceinline__ int rowmap(int i, int mode) {
    if (mode == 1) { int b = i / VP;  return b * SQ + (i - b * VP); }          // vision rows
    if (mode == 2) { int b = i / TLN; return b * SQ + VP + (i - b * TLN); }    // text rows
    return i;
}

__device__ __forceinline__ float blkSum(float v, float* sh) {
    int lane = threadIdx.x & 31, w = threadIdx.x >> 5, nw = blockDim.x >> 5;
    #pragma unroll
    for (int o = 16; o > 0; o >>= 1) v += __shfl_xor_sync(0xffffffffu, v, o);
    if (lane == 0) sh[w] = v;
    __syncthreads();
    v = (threadIdx.x < nw) ? sh[threadIdx.x] : 0.f;
    if (w == 0) {
        #pragma unroll
        for (int o = 4; o > 0; o >>= 1) v += __shfl_xor_sync(0xffffffffu, v, o);
        if (lane == 0) sh[0] = v;
    }
    __syncthreads();
    v = sh[0];
    __syncthreads();
    return v;
}

__device__ __forceinline__ float blkMax(float v, float* sh) {
    int lane = threadIdx.x & 31, w = threadIdx.x >> 5, nw = blockDim.x >> 5;
    #pragma unroll
    for (int o = 16; o > 0; o >>= 1) v = fmaxf(v, __shfl_xor_sync(0xffffffffu, v, o));
    if (lane == 0) sh[w] = v;
    __syncthreads();
    v = (threadIdx.x < nw) ? sh[threadIdx.x] : -3.4e38f;
    if (w == 0) {
        #pragma unroll
        for (int o = 4; o > 0; o >>= 1) v = fmaxf(v, __shfl_xor_sync(0xffffffffu, v, o));
        if (lane == 0) sh[0] = v;
    }
    __syncthreads();
    v = sh[0];
    __syncthreads();
    return v;
}

// ---------------- generic GEMM: C = act(A(map)·Wᵀ + bias), W is [N,K] row-major ----
// BM=BN=128, BK=8, 256 threads, 8x8 per thread.
__global__ __launch_bounds__(256, 2) void sgemm128(
    int M, int N, int K,
    const float* __restrict__ A, int lda, int mapA,
    const float* __restrict__ W,
    const float* __restrict__ bias,
    float* __restrict__ C, int ldc, int mapC,
    int act)
{
    __shared__ float As[8][132];
    __shared__ float Bs[8][132];
    int tid = threadIdx.x;
    int m0 = blockIdx.y * 128, n0 = blockIdx.x * 128;
    int tx = tid & 15, ty = tid >> 4;

    int aRow = tid >> 1;
    int aCol = (tid & 1) * 4;
    int arowg = m0 + aRow; if (arowg >= M) arowg = M - 1;
    const float* Aptr = A + (size_t)rowmap(arowg, mapA) * lda + aCol;
    const float* Wptr = W + (size_t)(n0 + aRow) * K + aCol;

    float acc[8][8];
    #pragma unroll
    for (int i = 0; i < 8; i++)
        #pragma unroll
        for (int j = 0; j < 8; j++) acc[i][j] = 0.f;

    for (int k0 = 0; k0 < K; k0 += 8) {
        float4 av = *(const float4*)(Aptr + k0);
        float4 bv = *(const float4*)(Wptr + k0);
        As[aCol + 0][aRow] = av.x; As[aCol + 1][aRow] = av.y;
        As[aCol + 2][aRow] = av.z; As[aCol + 3][aRow] = av.w;
        Bs[aCol + 0][aRow] = bv.x; Bs[aCol + 1][aRow] = bv.y;
        Bs[aCol + 2][aRow] = bv.z; Bs[aCol + 3][aRow] = bv.w;
        __syncthreads();
        #pragma unroll
        for (int k = 0; k < 8; k++) {
            float4 a0 = *(const float4*)&As[k][ty * 8];
            float4 a1 = *(const float4*)&As[k][ty * 8 + 4];
            float4 b0 = *(const float4*)&Bs[k][tx * 8];
            float4 b1 = *(const float4*)&Bs[k][tx * 8 + 4];
            float a[8] = {a0.x, a0.y, a0.z, a0.w, a1.x, a1.y, a1.z, a1.w};
            float b[8] = {b0.x, b0.y, b0.z, b0.w, b1.x, b1.y, b1.z, b1.w};
            #pragma unroll
            for (int i = 0; i < 8; i++)
                #pragma unroll
                for (int j = 0; j < 8; j++)
                    acc[i][j] += a[i] * b[j];
        }
        __syncthreads();
    }

    #pragma unroll
    for (int i = 0; i < 8; i++) {
        int mi = m0 + ty * 8 + i;
        if (mi < M) {
            size_t crow = (size_t)rowmap(mi, mapC) * ldc;
            #pragma unroll
            for (int j = 0; j < 8; j++) {
                int nj = n0 + tx * 8 + j;
                float v = acc[i][j] + bias[nj];
                if (act == 1) v = 0.5f * v * (1.f + erff(v * 0.70710678118654752f));
                C[crow + nj] = v;
            }
        }
    }
}

// ---------------- attention: scores = scale*Q·Kᵀ + key_bias ----------------
__global__ __launch_bounds__(256) void attn_scores(
    const float* __restrict__ qkv, const float* __restrict__ bias,
    float* __restrict__ sc)
{
    int bh = blockIdx.z; int b = bh >> 3, h = bh & 7;
    const float* Qb = qkv + (size_t)b * SQ * (3 * HDIM) + h * HD;
    const float* Kb = Qb + HDIM;
    __shared__ float Qs[16][68];
    __shared__ float Ks[16][68];
    int tid = threadIdx.x, tx = tid & 15, ty = tid >> 4;
    int q0 = blockIdx.y * 64, k0 = blockIdx.x * 64;
    int lRow = tid >> 2, lCol = (tid & 3) * 4;

    float acc[4][4];
    #pragma unroll
    for (int i = 0; i < 4; i++)
        #pragma unroll
        for (int j = 0; j < 4; j++) acc[i][j] = 0.f;

    for (int d0 = 0; d0 < HD; d0 += 16) {
        float4 qv = *(const float4*)(Qb + (size_t)(q0 + lRow) * (3 * HDIM) + d0 + lCol);
        float4 kv = *(const float4*)(Kb + (size_t)(k0 + lRow) * (3 * HDIM) + d0 + lCol);
        Qs[lCol + 0][lRow] = qv.x; Qs[lCol + 1][lRow] = qv.y;
        Qs[lCol + 2][lRow] = qv.z; Qs[lCol + 3][lRow] = qv.w;
        Ks[lCol + 0][lRow] = kv.x; Ks[lCol + 1][lRow] = kv.y;
        Ks[lCol + 2][lRow] = kv.z; Ks[lCol + 3][lRow] = kv.w;
        __syncthreads();
        #pragma unroll
        for (int k = 0; k < 16; k++) {
            float a[4], bb[4];
            #pragma unroll
            for (int i = 0; i < 4; i++) a[i] = Qs[k][ty * 4 + i];
            #pragma unroll
            for (int j = 0; j < 4; j++) bb[j] = Ks[k][tx * 4 + j];
            #pragma unroll
            for (int i = 0; i < 4; i++)
                #pragma unroll
                for (int j = 0; j < 4; j++)
                    acc[i][j] += a[i] * bb[j];
        }
        __syncthreads();
    }
    const float scale = 0.10206207261596575f;  // 1/sqrt(96)
    float* out = sc + ((size_t)bh * SQ + q0) * SQ + k0;
    const float* br = bias + b * SQ + k0;
    #pragma unroll
    for (int i = 0; i < 4; i++)
        #pragma unroll
        for (int j = 0; j < 4; j++)
            out[(ty * 4 + i) * SQ + tx * 4 + j] = acc[i][j] * scale + br[tx * 4 + j];
}

// ---------------- row softmax over 512 ----------------
__global__ void softmax512(float* __restrict__ sc) {
    __shared__ float sh[8];
    float* p = sc + (size_t)blockIdx.x * SQ;
    int t = threadIdx.x;  // 128
    float v0 = p[t], v1 = p[t + 128], v2 = p[t + 256], v3 = p[t + 384];
    float m = blkMax(fmaxf(fmaxf(v0, v1), fmaxf(v2, v3)), sh);
    v0 = expf(v0 - m); v1 = expf(v1 - m); v2 = expf(v2 - m); v3 = expf(v3 - m);
    float s = blkSum(v0 + v1 + v2 + v3, sh);
    float inv = 1.f / s;
    p[t] = v0 * inv; p[t + 128] = v1 * inv; p[t + 256] = v2 * inv; p[t + 384] = v3 * inv;
}

// ---------------- attention: AO = P·V ----------------
__global__ __launch_bounds__(256) void attn_pv(
    const float* __restrict__ sc, const float* __restrict__ qkv,
    float* __restrict__ ao)
{
    int bh = blockIdx.y; int b = bh >> 3, h = bh & 7;
    const float* P = sc + (size_t)bh * SQ * SQ;
    const float* V = qkv + (size_t)b * SQ * (3 * HDIM) + 2 * HDIM + h * HD;
    __shared__ float Ps[16][68];
    __shared__ float Vs[16][100];
    int tid = threadIdx.x, tx = tid & 15, ty = tid >> 4;
    int q0 = blockIdx.x * 64;
    int pRow = tid >> 2, pCol = (tid & 3) * 4;

    float acc[4][6];
    #pragma unroll
    for (int i = 0; i < 4; i++)
        #pragma unroll
        for (int j = 0; j < 6; j++) acc[i][j] = 0.f;

    for (int k0 = 0; k0 < SQ; k0 += 16) {
        float4 pv = *(const float4*)(P + (size_t)(q0 + pRow) * SQ + k0 + pCol);
        Ps[pCol + 0][pRow] = pv.x; Ps[pCol + 1][pRow] = pv.y;
        Ps[pCol + 2][pRow] = pv.z; Ps[pCol + 3][pRow] = pv.w;
        #pragma unroll
        for (int i = 0; i < 6; i++) {
            int idx = tid + i * 256;
            int vk = idx / 96, vn = idx - vk * 96;
            Vs[vk][vn] = V[(size_t)(k0 + vk) * (3 * HDIM) + vn];
        }
        __syncthreads();
        #pragma unroll
        for (int k = 0; k < 16; k++) {
            float a[4], bb[6];
            #pragma unroll
            for (int i = 0; i < 4; i++) a[i] = Ps[k][ty * 4 + i];
            #pragma unroll
            for (int j = 0; j < 6; j++) bb[j] = Vs[k][tx * 6 + j];
            #pragma unroll
            for (int i = 0; i < 4; i++)
                #pragma unroll
                for (int j = 0; j < 6; j++)
                    acc[i][j] += a[i] * bb[j];
        }
        __syncthreads();
    }
    float* orow = ao + ((size_t)b * SQ + q0) * HDIM + h * HD;
    #pragma unroll
    for (int i = 0; i < 4; i++)
        #pragma unroll
        for (int j = 0; j < 6; j++)
            orow[(ty * 4 + i) * HDIM + tx * 6 + j] = acc[i][j];
}

// ---------------- residual + LayerNorm (per-modality params) ----------------
__global__ void ln_row(const float* __restrict__ a, const float* __restrict__ res,
                       const float* __restrict__ g1, const float* __restrict__ b1,
                       const float* __restrict__ g2, const float* __restrict__ b2,
                       float* __restrict__ out)
{
    __shared__ float sh[8];
    int m = blockIdx.x;
    int s = m & (SQ - 1);
    const float* gg = (s < VP) ? g1 : g2;
    const float* bb = (s < VP) ? b1 : b2;
    const float* ar = a + (size_t)m * HDIM;
    const float* rr = res ? res + (size_t)m * HDIM : nullptr;
    int t = threadIdx.x;  // 256
    float v[3];
    float sum = 0.f;
    #pragma unroll
    for (int i = 0; i < 3; i++) {
        float xv = ar[t + i * 256];
        if (rr) xv += rr[t + i * 256];
        v[i] = xv; sum += xv;
    }
    float mean = blkSum(sum, sh) * (1.f / HDIM);
    float sq = 0.f;
    #pragma unroll
    for (int i = 0; i < 3; i++) { float d = v[i] - mean; sq += d * d; }
    float var = blkSum(sq, sh) * (1.f / HDIM);
    float inv = rsqrtf(var + 1e-5f);
    float* orow = out + (size_t)m * HDIM;
    #pragma unroll
    for (int i = 0; i < 3; i++) {
        int c = t + i * 256;
        orow[c] = (v[i] - mean) * inv * gg[c] + bb[c];
    }
}

// ---------------- key padding bias ----------------
// Mask arrives as a 4-byte-per-element buffer (bool converted to int32 by the
// harness; a nonzero word test is also correct if it were float32 1.0f).
__global__ void build_bias(const int* __restrict__ mask, float* __restrict__ bias) {
    int i = blockIdx.x * 256 + threadIdx.x;
    if (i < NB * SQ) {
        int s = i & (SQ - 1);
        float v = 0.f;
        if (s >= VP) {
            int b = i >> 9;
            v = (mask[b * TLN + (s - VP)] != 0) ? 0.f : -1e30f;
        }
        bias[i] = v;
    }
}

// ---------------- final output: x then combined_mask as float ----------------
__global__ void write_out(const float* __restrict__ x, const int* __restrict__ mask,
                          float* __restrict__ out, int out_size) {
    int n = blockIdx.x * 256 + threadIdx.x;
    if (n >= out_size) return;
    const int NX = MROWS * HDIM;
    if (n < NX) {
        out[n] = x[n];
    } else {
        int idx = n - NX;
        if (idx < NB * SQ) {
            int s = idx & (SQ - 1);
            int b = idx >> 9;
            out[n] = (s < VP) ? 1.f : ((mask[b * TLN + (s - VP)] != 0) ? 1.f : 0.f);
        }
    }
}

// ---------------- host ----------------
extern "C" void kernel_launch(void* const* d_in, const int* in_sizes, int n_in,
                              void* d_out, int out_size) {
    (void)in_sizes; (void)n_in;
    const float* vis   = (const float*)d_in[0];
    const float* txt   = (const float*)d_in[1];
    const int*   mask  = (const int*)d_in[2];
    const float* vp_w = (const float*)d_in[3];
    const float* vp_b = (const float*)d_in[4];
    const float* vp_g = (const float*)d_in[5];
    const float* vp_be= (const float*)d_in[6];
    const float* tp_w = (const float*)d_in[7];
    const float* tp_b = (const float*)d_in[8];
    const float* tp_g = (const float*)d_in[9];
    const float* tp_be= (const float*)d_in[10];
    const float* in_w = (const float*)d_in[11];
    const float* in_b = (const float*)d_in[12];
    const float* out_w= (const float*)d_in[13];
    const float* out_b= (const float*)d_in[14];
    const float* ln1g = (const float*)d_in[15];
    const float* ln1b = (const float*)d_in[16];
    const float* vew1 = (const float*)d_in[17];
    const float* veb1 = (const float*)d_in[18];
    const float* vew2 = (const float*)d_in[19];
    const float* veb2 = (const float*)d_in[20];
    const float* lew1 = (const float*)d_in[21];
    const float* leb1 = (const float*)d_in[22];
    const float* lew2 = (const float*)d_in[23];
    const float* leb2 = (const float*)d_in[24];
    const float* ln2g = (const float*)d_in[25];
    const float* ln2b = (const float*)d_in[26];

    float *x, *y, *qkv, *hb, *sc, *bias;
    cudaGetSymbolAddress((void**)&x,    g_x);
    cudaGetSymbolAddress((void**)&y,    g_y);
    cudaGetSymbolAddress((void**)&qkv,  g_qkv);
    cudaGetSymbolAddress((void**)&hb,   g_h);
    cudaGetSymbolAddress((void**)&sc,   g_sc);
    cudaGetSymbolAddress((void**)&bias, g_bias);

    // key-padding bias
    build_bias<<<32, 256>>>(mask, bias);

    // input projections -> x (mapped rows), then per-modality LN
    sgemm128<<<dim3(6, 25), 256>>>(3136, HDIM, VD,  vis, VD,   0, vp_w, vp_b, x, HDIM, 1, 0);
    sgemm128<<<dim3(6, 40), 256>>>(5056, HDIM, HDIM, txt, HDIM, 0, tp_w, tp_b, x, HDIM, 2, 0);
    ln_row<<<MROWS, 256>>>(x, nullptr, vp_g, vp_be, tp_g, tp_be, x);

    for (int i = 0; i < NLAYER; i++) {
        const float* iw  = in_w  + (size_t)i * 3 * HDIM * HDIM;
        const float* ib  = in_b  + (size_t)i * 3 * HDIM;
        const float* ow  = out_w + (size_t)i * HDIM * HDIM;
        const float* ob  = out_b + (size_t)i * HDIM;
        const float* l1g = ln1g + (size_t)i * HDIM;
        const float* l1b = ln1b + (size_t)i * HDIM;
        const float* l2g = ln2g + (size_t)i * HDIM;
        const float* l2b = ln2b + (size_t)i * HDIM;
        const float* vw1 = vew1 + (size_t)i * FFD * HDIM;
        const float* vb1 = veb1 + (size_t)i * FFD;
        const float* vw2 = vew2 + (size_t)i * HDIM * FFD;
        const float* vb2 = veb2 + (size_t)i * HDIM;
        const float* lw1 = lew1 + (size_t)i * FFD * HDIM;
        const float* lb1 = leb1 + (size_t)i * FFD;
        const float* lw2 = lew2 + (size_t)i * HDIM * FFD;
        const float* lb2 = leb2 + (size_t)i * HDIM;

        // QKV projection
        sgemm128<<<dim3(18, 64), 256>>>(MROWS, 3 * HDIM, HDIM, x, HDIM, 0, iw, ib, qkv, 3 * HDIM, 0, 0);
        // attention
        attn_scores<<<dim3(8, 8, NB * NHEAD), 256>>>(qkv, bias, sc);
        softmax512<<<NB * NHEAD * SQ, 128>>>(sc);
        attn_pv<<<dim3(8, NB * NHEAD), 256>>>(sc, qkv, y);
        // out projection -> hb (used as [8192,768] tmp)
        sgemm128<<<dim3(6, 64), 256>>>(MROWS, HDIM, HDIM, y, HDIM, 0, ow, ob, hb, HDIM, 0, 0);
        // x = LN(x + attn)
        ln_row<<<MROWS, 256>>>(x, hb, l1g, l1b, l1g, l1b, x);
        // dual-expert FFN (GELU) via row-remapped GEMMs
        sgemm128<<<dim3(24, 25), 256>>>(3136, FFD, HDIM, x, HDIM, 1, vw1, vb1, hb, FFD, 1, 1);
        sgemm128<<<dim3(24, 40), 256>>>(5056, FFD, HDIM, x, HDIM, 2, lw1, lb1, hb, FFD, 2, 1);
        sgemm128<<<dim3(6, 25), 256>>>(3136, HDIM, FFD, hb, FFD, 1, vw2, vb2, y, HDIM, 1, 0);
        sgemm128<<<dim3(6, 40), 256>>>(5056, HDIM, FFD, hb, FFD, 2, lw2, lb2, y, HDIM, 2, 0);
        // x = LN(x + ffn)
        ln_row<<<MROWS, 256>>>(x, y, l2g, l2b, l2g, l2b, x);
    }

    write_out<<<(out_size + 255) / 256, 256>>>(x, mask, (float*)d_out, out_size);
}

// round 6
// speedup vs baseline: 1.6061x; 1.6061x over previous
#include <cuda_runtime.h>
#include <cuda_bf16.h>
#include <math.h>
#include <stdint.h>

#define VP 196
#define TLN 316
#define SQ 512
#define VD 1024
#define HDIM 768
#define NHEAD 8
#define HD 96
#define FFD 3072
#define NLAYER 6
#define NB 16
#define MROWS (NB*SQ)   /* 8192 */

// ---------------- scratch (device globals; no allocations) ----------------
__device__ float g_x[MROWS*HDIM];        // residual stream
__device__ float g_y[MROWS*HDIM];        // attn-out / ffn-out
__device__ float g_qkv[MROWS*3*HDIM];
__device__ float g_h[MROWS*FFD];         // ffn hidden / proj tmp
__device__ float g_sc[NB*NHEAD*SQ*SQ];   // attention scores
__device__ float g_bias[NB*SQ];          // key-padding bias

// ---------------- helpers ----------------
__device__ __forceinline__ int rowmap(int i, int mode) {
    if (mode == 1) { int b = i / VP;  return b * SQ + (i - b * VP); }          // vision rows
    if (mode == 2) { int b = i / TLN; return b * SQ + VP + (i - b * TLN); }    // text rows
    return i;
}

__device__ __forceinline__ float blkSum(float v, float* sh) {
    int lane = threadIdx.x & 31, w = threadIdx.x >> 5, nw = blockDim.x >> 5;
    #pragma unroll
    for (int o = 16; o > 0; o >>= 1) v += __shfl_xor_sync(0xffffffffu, v, o);
    if (lane == 0) sh[w] = v;
    __syncthreads();
    v = (threadIdx.x < nw) ? sh[threadIdx.x] : 0.f;
    if (w == 0) {
        #pragma unroll
        for (int o = 4; o > 0; o >>= 1) v += __shfl_xor_sync(0xffffffffu, v, o);
        if (lane == 0) sh[0] = v;
    }
    __syncthreads();
    v = sh[0];
    __syncthreads();
    return v;
}

__device__ __forceinline__ float blkMax(float v, float* sh) {
    int lane = threadIdx.x & 31, w = threadIdx.x >> 5, nw = blockDim.x >> 5;
    #pragma unroll
    for (int o = 16; o > 0; o >>= 1) v = fmaxf(v, __shfl_xor_sync(0xffffffffu, v, o));
    if (lane == 0) sh[w] = v;
    __syncthreads();
    v = (threadIdx.x < nw) ? sh[threadIdx.x] : -3.4e38f;
    if (w == 0) {
        #pragma unroll
        for (int o = 4; o > 0; o >>= 1) v = fmaxf(v, __shfl_xor_sync(0xffffffffu, v, o));
        if (lane == 0) sh[0] = v;
    }
    __syncthreads();
    v = sh[0];
    __syncthreads();
    return v;
}

// ================= tensor-core GEMM: C = act(A(map)·Wᵀ + bias) =================
// Split-bf16 (bf16x3) fp32 emulation: A = Ah + Al, W = Wh + Wl;
// acc += Ah·Wh + Ah·Wl + Al·Wh (fp32 accum).  W is [N,K] row-major == B col-major.
// CTA tile 128x128x16, 8 warps (2x4), warp tile 64x32, mma m16n8k16.

#define SB 18   // smem row stride in bf16 elems (pad 16 -> 18: 9-bank stride, conflict-free)

__device__ __forceinline__ void mma_bf16(float* c, const uint32_t* a, const uint32_t* b) {
    asm volatile(
        "mma.sync.aligned.m16n8k16.row.col.f32.bf16.bf16.f32 "
        "{%0,%1,%2,%3}, {%4,%5,%6,%7}, {%8,%9}, {%0,%1,%2,%3};"
        : "+f"(c[0]), "+f"(c[1]), "+f"(c[2]), "+f"(c[3])
        : "r"(a[0]), "r"(a[1]), "r"(a[2]), "r"(a[3]), "r"(b[0]), "r"(b[1]));
}

__device__ __forceinline__ void cvt_pair(__nv_bfloat16* H, __nv_bfloat16* L,
                                         int off, float v0, float v1) {
    __nv_bfloat16 h0 = __float2bfloat16_rn(v0);
    __nv_bfloat16 h1 = __float2bfloat16_rn(v1);
    *(__nv_bfloat162*)(H + off) = __halves2bfloat162(h0, h1);
    __nv_bfloat16 l0 = __float2bfloat16_rn(v0 - __bfloat162float(h0));
    __nv_bfloat16 l1 = __float2bfloat16_rn(v1 - __bfloat162float(h1));
    *(__nv_bfloat162*)(L + off) = __halves2bfloat162(l0, l1);
}

__global__ __launch_bounds__(256, 2) void gemm_tc(
    int M, int N, int K,
    const float* __restrict__ A, int lda, int mapA,
    const float* __restrict__ W,
    const float* __restrict__ bias,
    float* __restrict__ C, int ldc, int mapC,
    int act)
{
    __shared__ __nv_bfloat16 Ah[128*SB], Al[128*SB], Bh[128*SB], Bl[128*SB];
    int tid = threadIdx.x;
    int m0 = blockIdx.y * 128, n0 = blockIdx.x * 128;
    int wid = tid >> 5, lane = tid & 31;
    int wm = wid >> 2, wn = wid & 3;          // warp origin (wm*64, wn*32)

    // gmem staging: thread -> (row = tid/2, col8 = (tid&1)*8)
    int lrow = tid >> 1, lcol = (tid & 1) * 8;
    int arow = m0 + lrow; if (arow >= M) arow = M - 1;
    const float* Ap = A + (size_t)rowmap(arow, mapA) * lda + lcol;
    const float* Wp = W + (size_t)(n0 + lrow) * K + lcol;

    float acc[16][4];
    #pragma unroll
    for (int i = 0; i < 16; i++)
        #pragma unroll
        for (int j = 0; j < 4; j++) acc[i][j] = 0.f;

    int qr = lane >> 2;            // 0..7
    int kk = (lane & 3) * 2;       // 0,2,4,6

    for (int k0 = 0; k0 < K; k0 += 16) {
        float4 a0v = *(const float4*)(Ap + k0);
        float4 a1v = *(const float4*)(Ap + k0 + 4);
        float4 b0v = *(const float4*)(Wp + k0);
        float4 b1v = *(const float4*)(Wp + k0 + 4);
        int so = lrow * SB + lcol;
        cvt_pair(Ah, Al, so + 0, a0v.x, a0v.y);
        cvt_pair(Ah, Al, so + 2, a0v.z, a0v.w);
        cvt_pair(Ah, Al, so + 4, a1v.x, a1v.y);
        cvt_pair(Ah, Al, so + 6, a1v.z, a1v.w);
        cvt_pair(Bh, Bl, so + 0, b0v.x, b0v.y);
        cvt_pair(Bh, Bl, so + 2, b0v.z, b0v.w);
        cvt_pair(Bh, Bl, so + 4, b1v.x, b1v.y);
        cvt_pair(Bh, Bl, so + 6, b1v.z, b1v.w);
        __syncthreads();

        // fragments
        uint32_t afh[4][4], afl[4][4], bfh[4][2], bfl[4][2];
        #pragma unroll
        for (int mt = 0; mt < 4; mt++) {
            int base = (wm * 64 + mt * 16 + qr) * SB;
            afh[mt][0] = *(const uint32_t*)&Ah[base + kk];
            afh[mt][1] = *(const uint32_t*)&Ah[base + 8 * SB + kk];
            afh[mt][2] = *(const uint32_t*)&Ah[base + kk + 8];
            afh[mt][3] = *(const uint32_t*)&Ah[base + 8 * SB + kk + 8];
            afl[mt][0] = *(const uint32_t*)&Al[base + kk];
            afl[mt][1] = *(const uint32_t*)&Al[base + 8 * SB + kk];
            afl[mt][2] = *(const uint32_t*)&Al[base + kk + 8];
            afl[mt][3] = *(const uint32_t*)&Al[base + 8 * SB + kk + 8];
        }
        #pragma unroll
        for (int nt = 0; nt < 4; nt++) {
            int nb = (wn * 32 + nt * 8 + qr) * SB;
            bfh[nt][0] = *(const uint32_t*)&Bh[nb + kk];
            bfh[nt][1] = *(const uint32_t*)&Bh[nb + kk + 8];
            bfl[nt][0] = *(const uint32_t*)&Bl[nb + kk];
            bfl[nt][1] = *(const uint32_t*)&Bl[nb + kk + 8];
        }
        #pragma unroll
        for (int mt = 0; mt < 4; mt++)
            #pragma unroll
            for (int nt = 0; nt < 4; nt++) {
                float* c = acc[mt * 4 + nt];
                mma_bf16(c, afh[mt], bfh[nt]);
                mma_bf16(c, afh[mt], bfl[nt]);
                mma_bf16(c, afl[mt], bfh[nt]);
            }
        __syncthreads();
    }

    // epilogue: bias (+ optional erf-GELU), row-remapped store
    #pragma unroll
    for (int mt = 0; mt < 4; mt++) {
        #pragma unroll
        for (int nt = 0; nt < 4; nt++) {
            const float* c = acc[mt * 4 + nt];
            int r = m0 + wm * 64 + mt * 16 + qr;
            int cn = n0 + wn * 32 + nt * 8 + (lane & 3) * 2;
            float bz0 = bias[cn], bz1 = bias[cn + 1];
            #pragma unroll
            for (int half = 0; half < 2; half++) {
                int rr = r + half * 8;
                if (rr < M) {
                    float v0 = c[half * 2 + 0] + bz0;
                    float v1 = c[half * 2 + 1] + bz1;
                    if (act == 1) {
                        v0 = 0.5f * v0 * (1.f + erff(v0 * 0.70710678118654752f));
                        v1 = 0.5f * v1 * (1.f + erff(v1 * 0.70710678118654752f));
                    }
                    float* dst = C + (size_t)rowmap(rr, mapC) * ldc + cn;
                    dst[0] = v0; dst[1] = v1;
                }
            }
        }
    }
}

// ---------------- attention: scores = scale*Q·Kᵀ + key_bias ----------------
__global__ __launch_bounds__(256) void attn_scores(
    const float* __restrict__ qkv, const float* __restrict__ bias,
    float* __restrict__ sc)
{
    int bh = blockIdx.z; int b = bh >> 3, h = bh & 7;
    const float* Qb = qkv + (size_t)b * SQ * (3 * HDIM) + h * HD;
    const float* Kb = Qb + HDIM;
    __shared__ float Qs[16][68];
    __shared__ float Ks[16][68];
    int tid = threadIdx.x, tx = tid & 15, ty = tid >> 4;
    int q0 = blockIdx.y * 64, k0 = blockIdx.x * 64;
    int lRow = tid >> 2, lCol = (tid & 3) * 4;

    float acc[4][4];
    #pragma unroll
    for (int i = 0; i < 4; i++)
        #pragma unroll
        for (int j = 0; j < 4; j++) acc[i][j] = 0.f;

    for (int d0 = 0; d0 < HD; d0 += 16) {
        float4 qv = *(const float4*)(Qb + (size_t)(q0 + lRow) * (3 * HDIM) + d0 + lCol);
        float4 kv = *(const float4*)(Kb + (size_t)(k0 + lRow) * (3 * HDIM) + d0 + lCol);
        Qs[lCol + 0][lRow] = qv.x; Qs[lCol + 1][lRow] = qv.y;
        Qs[lCol + 2][lRow] = qv.z; Qs[lCol + 3][lRow] = qv.w;
        Ks[lCol + 0][lRow] = kv.x; Ks[lCol + 1][lRow] = kv.y;
        Ks[lCol + 2][lRow] = kv.z; Ks[lCol + 3][lRow] = kv.w;
        __syncthreads();
        #pragma unroll
        for (int k = 0; k < 16; k++) {
            float a[4], bb[4];
            #pragma unroll
            for (int i = 0; i < 4; i++) a[i] = Qs[k][ty * 4 + i];
            #pragma unroll
            for (int j = 0; j < 4; j++) bb[j] = Ks[k][tx * 4 + j];
            #pragma unroll
            for (int i = 0; i < 4; i++)
                #pragma unroll
                for (int j = 0; j < 4; j++)
                    acc[i][j] += a[i] * bb[j];
        }
        __syncthreads();
    }
    const float scale = 0.10206207261596575f;  // 1/sqrt(96)
    float* out = sc + ((size_t)bh * SQ + q0) * SQ + k0;
    const float* br = bias + b * SQ + k0;
    #pragma unroll
    for (int i = 0; i < 4; i++)
        #pragma unroll
        for (int j = 0; j < 4; j++)
            out[(ty * 4 + i) * SQ + tx * 4 + j] = acc[i][j] * scale + br[tx * 4 + j];
}

// ---------------- row softmax over 512 ----------------
__global__ void softmax512(float* __restrict__ sc) {
    __shared__ float sh[8];
    float* p = sc + (size_t)blockIdx.x * SQ;
    int t = threadIdx.x;  // 128
    float v0 = p[t], v1 = p[t + 128], v2 = p[t + 256], v3 = p[t + 384];
    float m = blkMax(fmaxf(fmaxf(v0, v1), fmaxf(v2, v3)), sh);
    v0 = expf(v0 - m); v1 = expf(v1 - m); v2 = expf(v2 - m); v3 = expf(v3 - m);
    float s = blkSum(v0 + v1 + v2 + v3, sh);
    float inv = 1.f / s;
    p[t] = v0 * inv; p[t + 128] = v1 * inv; p[t + 256] = v2 * inv; p[t + 384] = v3 * inv;
}

// ---------------- attention: AO = P·V ----------------
__global__ __launch_bounds__(256) void attn_pv(
    const float* __restrict__ sc, const float* __restrict__ qkv,
    float* __restrict__ ao)
{
    int bh = blockIdx.y; int b = bh >> 3, h = bh & 7;
    const float* P = sc + (size_t)bh * SQ * SQ;
    const float* V = qkv + (size_t)b * SQ * (3 * HDIM) + 2 * HDIM + h * HD;
    __shared__ float Ps[16][68];
    __shared__ float Vs[16][100];
    int tid = threadIdx.x, tx = tid & 15, ty = tid >> 4;
    int q0 = blockIdx.x * 64;
    int pRow = tid >> 2, pCol = (tid & 3) * 4;

    float acc[4][6];
    #pragma unroll
    for (int i = 0; i < 4; i++)
        #pragma unroll
        for (int j = 0; j < 6; j++) acc[i][j] = 0.f;

    for (int k0 = 0; k0 < SQ; k0 += 16) {
        float4 pv = *(const float4*)(P + (size_t)(q0 + pRow) * SQ + k0 + pCol);
        Ps[pCol + 0][pRow] = pv.x; Ps[pCol + 1][pRow] = pv.y;
        Ps[pCol + 2][pRow] = pv.z; Ps[pCol + 3][pRow] = pv.w;
        #pragma unroll
        for (int i = 0; i < 6; i++) {
            int idx = tid + i * 256;
            int vk = idx / 96, vn = idx - vk * 96;
            Vs[vk][vn] = V[(size_t)(k0 + vk) * (3 * HDIM) + vn];
        }
        __syncthreads();
        #pragma unroll
        for (int k = 0; k < 16; k++) {
            float a[4], bb[6];
            #pragma unroll
            for (int i = 0; i < 4; i++) a[i] = Ps[k][ty * 4 + i];
            #pragma unroll
            for (int j = 0; j < 6; j++) bb[j] = Vs[k][tx * 6 + j];
            #pragma unroll
            for (int i = 0; i < 4; i++)
                #pragma unroll
                for (int j = 0; j < 6; j++)
                    acc[i][j] += a[i] * bb[j];
        }
        __syncthreads();
    }
    float* orow = ao + ((size_t)b * SQ + q0) * HDIM + h * HD;
    #pragma unroll
    for (int i = 0; i < 4; i++)
        #pragma unroll
        for (int j = 0; j < 6; j++)
            orow[(ty * 4 + i) * HDIM + tx * 6 + j] = acc[i][j];
}

// ---------------- residual + LayerNorm (per-modality params) ----------------
__global__ void ln_row(const float* __restrict__ a, const float* __restrict__ res,
                       const float* __restrict__ g1, const float* __restrict__ b1,
                       const float* __restrict__ g2, const float* __restrict__ b2,
                       float* __restrict__ out)
{
    __shared__ float sh[8];
    int m = blockIdx.x;
    int s = m & (SQ - 1);
    const float* gg = (s < VP) ? g1 : g2;
    const float* bb = (s < VP) ? b1 : b2;
    const float* ar = a + (size_t)m * HDIM;
    const float* rr = res ? res + (size_t)m * HDIM : nullptr;
    int t = threadIdx.x;  // 256
    float v[3];
    float sum = 0.f;
    #pragma unroll
    for (int i = 0; i < 3; i++) {
        float xv = ar[t + i * 256];
        if (rr) xv += rr[t + i * 256];
        v[i] = xv; sum += xv;
    }
    float mean = blkSum(sum, sh) * (1.f / HDIM);
    float sq = 0.f;
    #pragma unroll
    for (int i = 0; i < 3; i++) { float d = v[i] - mean; sq += d * d; }
    float var = blkSum(sq, sh) * (1.f / HDIM);
    float inv = rsqrtf(var + 1e-5f);
    float* orow = out + (size_t)m * HDIM;
    #pragma unroll
    for (int i = 0; i < 3; i++) {
        int c = t + i * 256;
        orow[c] = (v[i] - mean) * inv * gg[c] + bb[c];
    }
}

// ---------------- key padding bias (mask is 4-byte words; nonzero == true) ----
__global__ void build_bias(const int* __restrict__ mask, float* __restrict__ bias) {
    int i = blockIdx.x * 256 + threadIdx.x;
    if (i < NB * SQ) {
        int s = i & (SQ - 1);
        float v = 0.f;
        if (s >= VP) {
            int b = i >> 9;
            v = (mask[b * TLN + (s - VP)] != 0) ? 0.f : -1e30f;
        }
        bias[i] = v;
    }
}

// ---------------- final output: x then combined_mask as float ----------------
__global__ void write_out(const float* __restrict__ x, const int* __restrict__ mask,
                          float* __restrict__ out, int out_size) {
    int n = blockIdx.x * 256 + threadIdx.x;
    if (n >= out_size) return;
    const int NX = MROWS * HDIM;
    if (n < NX) {
        out[n] = x[n];
    } else {
        int idx = n - NX;
        if (idx < NB * SQ) {
            int s = idx & (SQ - 1);
            int b = idx >> 9;
            out[n] = (s < VP) ? 1.f : ((mask[b * TLN + (s - VP)] != 0) ? 1.f : 0.f);
        }
    }
}

// ---------------- host ----------------
extern "C" void kernel_launch(void* const* d_in, const int* in_sizes, int n_in,
                              void* d_out, int out_size) {
    (void)in_sizes; (void)n_in;
    const float* vis   = (const float*)d_in[0];
    const float* txt   = (const float*)d_in[1];
    const int*   mask  = (const int*)d_in[2];
    const float* vp_w = (const float*)d_in[3];
    const float* vp_b = (const float*)d_in[4];
    const float* vp_g = (const float*)d_in[5];
    const float* vp_be= (const float*)d_in[6];
    const float* tp_w = (const float*)d_in[7];
    const float* tp_b = (const float*)d_in[8];
    const float* tp_g = (const float*)d_in[9];
    const float* tp_be= (const float*)d_in[10];
    const float* in_w = (const float*)d_in[11];
    const float* in_b = (const float*)d_in[12];
    const float* out_w= (const float*)d_in[13];
    const float* out_b= (const float*)d_in[14];
    const float* ln1g = (const float*)d_in[15];
    const float* ln1b = (const float*)d_in[16];
    const float* vew1 = (const float*)d_in[17];
    const float* veb1 = (const float*)d_in[18];
    const float* vew2 = (const float*)d_in[19];
    const float* veb2 = (const float*)d_in[20];
    const float* lew1 = (const float*)d_in[21];
    const float* leb1 = (const float*)d_in[22];
    const float* lew2 = (const float*)d_in[23];
    const float* leb2 = (const float*)d_in[24];
    const float* ln2g = (const float*)d_in[25];
    const float* ln2b = (const float*)d_in[26];

    float *x, *y, *qkv, *hb, *sc, *bias;
    cudaGetSymbolAddress((void**)&x,    g_x);
    cudaGetSymbolAddress((void**)&y,    g_y);
    cudaGetSymbolAddress((void**)&qkv,  g_qkv);
    cudaGetSymbolAddress((void**)&hb,   g_h);
    cudaGetSymbolAddress((void**)&sc,   g_sc);
    cudaGetSymbolAddress((void**)&bias, g_bias);

    // key-padding bias
    build_bias<<<32, 256>>>(mask, bias);

    // input projections -> x (mapped rows), then per-modality LN
    gemm_tc<<<dim3(6, 25), 256>>>(3136, HDIM, VD,  vis, VD,   0, vp_w, vp_b, x, HDIM, 1, 0);
    gemm_tc<<<dim3(6, 40), 256>>>(5056, HDIM, HDIM, txt, HDIM, 0, tp_w, tp_b, x, HDIM, 2, 0);
    ln_row<<<MROWS, 256>>>(x, nullptr, vp_g, vp_be, tp_g, tp_be, x);

    for (int i = 0; i < NLAYER; i++) {
        const float* iw  = in_w  + (size_t)i * 3 * HDIM * HDIM;
        const float* ib  = in_b  + (size_t)i * 3 * HDIM;
        const float* ow  = out_w + (size_t)i * HDIM * HDIM;
        const float* ob  = out_b + (size_t)i * HDIM;
        const float* l1g = ln1g + (size_t)i * HDIM;
        const float* l1b = ln1b + (size_t)i * HDIM;
        const float* l2g = ln2g + (size_t)i * HDIM;
        const float* l2b = ln2b + (size_t)i * HDIM;
        const float* vw1 = vew1 + (size_t)i * FFD * HDIM;
        const float* vb1 = veb1 + (size_t)i * FFD;
        const float* vw2 = vew2 + (size_t)i * HDIM * FFD;
        const float* vb2 = veb2 + (size_t)i * HDIM;
        const float* lw1 = lew1 + (size_t)i * FFD * HDIM;
        const float* lb1 = leb1 + (size_t)i * FFD;
        const float* lw2 = lew2 + (size_t)i * HDIM * FFD;
        const float* lb2 = leb2 + (size_t)i * HDIM;

        // QKV projection
        gemm_tc<<<dim3(18, 64), 256>>>(MROWS, 3 * HDIM, HDIM, x, HDIM, 0, iw, ib, qkv, 3 * HDIM, 0, 0);
        // attention
        attn_scores<<<dim3(8, 8, NB * NHEAD), 256>>>(qkv, bias, sc);
        softmax512<<<NB * NHEAD * SQ, 128>>>(sc);
        attn_pv<<<dim3(8, NB * NHEAD), 256>>>(sc, qkv, y);
        // out projection -> hb (used as [8192,768] tmp)
        gemm_tc<<<dim3(6, 64), 256>>>(MROWS, HDIM, HDIM, y, HDIM, 0, ow, ob, hb, HDIM, 0, 0);
        // x = LN(x + attn)
        ln_row<<<MROWS, 256>>>(x, hb, l1g, l1b, l1g, l1b, x);
        // dual-expert FFN (GELU) via row-remapped GEMMs
        gemm_tc<<<dim3(24, 25), 256>>>(3136, FFD, HDIM, x, HDIM, 1, vw1, vb1, hb, FFD, 1, 1);
        gemm_tc<<<dim3(24, 40), 256>>>(5056, FFD, HDIM, x, HDIM, 2, lw1, lb1, hb, FFD, 2, 1);
        gemm_tc<<<dim3(6, 25), 256>>>(3136, HDIM, FFD, hb, FFD, 1, vw2, vb2, y, HDIM, 1, 0);
        gemm_tc<<<dim3(6, 40), 256>>>(5056, HDIM, FFD, hb, FFD, 2, lw2, lb2, y, HDIM, 2, 0);
        // x = LN(x + ffn)
        ln_row<<<MROWS, 256>>>(x, y, l2g, l2b, l2g, l2b, x);
    }

    write_out<<<(out_size + 255) / 256, 256>>>(x, mask, (float*)d_out, out_size);
}